// round 16
// baseline (speedup 1.0000x reference)
#include <cuda_runtime.h>
#include <cuda_fp16.h>
#include <cstdint>
#include <math.h>

// ---------------------------------------------------------------------------
// Fixed problem: B=4, S=2048, D=DK=1024. M = B*S = 8192.
// R16: R15 + (a) gemm_wm split-K=8 with fused last-CTA reduction (atomic
// counter, self-resetting), (b) warp-per-row conv_x_t. Engine/algebra frozen.
// ---------------------------------------------------------------------------
#define BATCH 4
#define SEQ   2048
#define DIM   1024
#define DKV   1024
#define MTOT  (BATCH * SEQ)

#define TILE  128
#define KC    64          // fp16 elements per K-chunk (128B rows, SW128)
#define WMSPLIT 8
#define WMKLEN  (DIM / WMSPLIT)   // 128

// ---------------- scratch (device globals; no allocation) -------------------
__device__ __half g_x16[(size_t)MTOT * DIM];
__device__ __half g_wq16[(size_t)DIM * DKV];             // Wq fp16 (plain)
__device__ __half g_wk16[(size_t)DIM * DKV];             // Wk fp16 (plain)
__device__ __half g_wvt16[(size_t)DKV * DIM];            // Wv^T fp16
__device__ __half g_mt16[(size_t)DIM * DIM];             // (Wq Wk^T)^T fp16
__device__ float  g_mpart[(size_t)WMSPLIT * DIM * DIM];  // split-K partials (T)
__device__ int    g_wmcnt[64];                           // per-tile arrival cnt
__device__ __half g_g16[(size_t)MTOT * DIM];             // G = x M
__device__ __half g_vt16[(size_t)MTOT * DKV];            // V^T per batch
__device__ __half g_E [(size_t)BATCH * SEQ * SEQ];       // exp(scores), fp16
__device__ float  g_rsum[(size_t)MTOT * 16];
__device__ float  g_wt[DIM];                             // Wk bq
__device__ float  g_t [(size_t)MTOT];                    // x (Wk bq)

// ---------------- PTX helpers ----------------------------------------------
static __device__ __forceinline__ uint32_t smem_u32(const void* p) {
    uint32_t a;
    asm("{ .reg .u64 t; cvta.to.shared.u64 t, %1; cvt.u32.u64 %0, t; }" : "=r"(a) : "l"(p));
    return a;
}
static __device__ __forceinline__ void cp16(uint32_t dst, const void* src) {
    asm volatile("cp.async.cg.shared.global [%0], [%1], 16;" :: "r"(dst), "l"(src) : "memory");
}
static __device__ __forceinline__ void cp_commit() {
    asm volatile("cp.async.commit_group;" ::: "memory");
}
static __device__ __forceinline__ void ldsm4(uint32_t* r, uint32_t addr) {
    asm volatile("ldmatrix.sync.aligned.m8n8.x4.shared.b16 {%0,%1,%2,%3}, [%4];"
                 : "=r"(r[0]), "=r"(r[1]), "=r"(r[2]), "=r"(r[3]) : "r"(addr));
}
static __device__ __forceinline__ void mma16816(float* c, const uint32_t* a, const uint32_t* b) {
    asm volatile(
        "mma.sync.aligned.m16n8k16.row.col.f32.f16.f16.f32 "
        "{%0,%1,%2,%3}, {%4,%5,%6,%7}, {%8,%9}, {%0,%1,%2,%3};"
        : "+f"(c[0]), "+f"(c[1]), "+f"(c[2]), "+f"(c[3])
        : "r"(a[0]), "r"(a[1]), "r"(a[2]), "r"(a[3]), "r"(b[0]), "r"(b[1]));
}
static __device__ __forceinline__ uint32_t sw128(uint32_t off) {
    return off ^ ((off >> 3) & 0x70);
}

// Stage (32KB): A @0 (16KB), B @16KB. 128 rows x 128B, SW128 swizzle.
#define STAGE_BYTES 32768
#define NSTAGE      3
#define SMEM_BYTES  (1024 + NSTAGE * STAGE_BYTES)

static __device__ __forceinline__ void load_chunk(
    const __half* A, const __half* B, int Kst,
    int m0, int n0, int koff, uint32_t stage, int tid)
{
    #pragma unroll
    for (int j = 0; j < 4; j++) {
        int id = tid + j * 256;                 // 0..1023
        int r  = id >> 3;                       // 0..127
        int cb = (id & 7) << 4;                 // byte col in 128B row
        uint32_t sw = sw128((uint32_t)((r << 7) + cb));
        cp16(stage +         sw, A + (long)(m0 + r) * Kst + koff + (cb >> 1));
        cp16(stage + 16384 + sw, B + (long)(n0 + r) * Kst + koff + (cb >> 1));
    }
    cp_commit();
}

// Shared prolog + pipelined mainloop + accumulator->tile spill (R11 engine).
// Kst = row stride of A/B; Klen = contraction length for this CTA.
#define GEMM_BODY2(Aptr, Bptr, Kst, Klen)                                        \
    extern __shared__ char smraw[];                                              \
    const int tid = threadIdx.x;                                                 \
    const int wid = tid >> 5;                                                    \
    const int lid = tid & 31;                                                    \
    const int z   = blockIdx.z;                                                  \
    const int m0  = blockIdx.y * TILE;                                           \
    const int n0  = blockIdx.x * TILE;                                           \
    const uint32_t smb = (smem_u32(smraw) + 1023u) & ~1023u;                     \
    uint32_t stg[NSTAGE];                                                        \
    _Pragma("unroll")                                                            \
    for (int s = 0; s < NSTAGE; s++) stg[s] = smb + s * STAGE_BYTES;             \
    const int wm = (wid >> 2) * 64;                                              \
    const int wn = (wid & 3) * 32;                                               \
    const int aRow  = wm + (lid & 15);                                           \
    const int aColB = (lid >> 4) << 4;                                           \
    const int bRow  = wn + (((lid >> 4) & 1) << 3) + (lid & 7);                  \
    const int bColB = ((lid >> 3) & 1) << 4;                                     \
    uint32_t aOff[4], bOff[2];                                                   \
    _Pragma("unroll")                                                            \
    for (int t = 0; t < 4; t++)                                                  \
        aOff[t] = sw128((uint32_t)((aRow + t * 16) << 7) + aColB);               \
    _Pragma("unroll")                                                            \
    for (int t = 0; t < 2; t++)                                                  \
        bOff[t] = sw128((uint32_t)((bRow + t * 16) << 7) + bColB) + 16384;       \
    float acc[4][4][4];                                                          \
    _Pragma("unroll")                                                            \
    for (int mi = 0; mi < 4; mi++)                                               \
        _Pragma("unroll")                                                        \
        for (int ni = 0; ni < 4; ni++)                                           \
            _Pragma("unroll")                                                    \
            for (int r = 0; r < 4; r++) acc[mi][ni][r] = 0.0f;                   \
    uint32_t fa[2][4], fb[2][8];                                                 \
    const int NC = (Klen) / KC;                                                  \
    load_chunk((Aptr), (Bptr), (Kst), m0, n0, 0, stg[0], tid);                   \
    load_chunk((Aptr), (Bptr), (Kst), m0, n0, KC, stg[1], tid);                  \
    uint32_t cur = stg[0];                                                       \
    int nxt = 2;                                                                 \
    for (int i = 0; i < NC; i++) {                                               \
        asm volatile("cp.async.wait_group 1;" ::: "memory");                     \
        __syncthreads();                                                         \
        if (i + 2 < NC)                                                          \
            load_chunk((Aptr), (Bptr), (Kst), m0, n0, (i + 2) * KC, stg[nxt], tid); \
        else                                                                     \
            cp_commit();                                                         \
        ldsm4(&fb[0][0], cur + bOff[0]);                                         \
        ldsm4(&fb[0][4], cur + bOff[1]);                                         \
        ldsm4(fa[0],     cur + aOff[0]);                                         \
        _Pragma("unroll")                                                        \
        for (int kk = 0; kk < 4; kk++) {                                         \
            const uint32_t xc = (uint32_t)(kk << 5);                             \
            const uint32_t xn = (uint32_t)((kk + 1) << 5);                       \
            _Pragma("unroll")                                                    \
            for (int mi = 0; mi < 4; mi++) {                                     \
                const int p  = (kk * 4 + mi) & 1;                                \
                const int np = p ^ 1;                                            \
                if (mi < 3) {                                                    \
                    ldsm4(fa[np], cur + (aOff[mi + 1] ^ xc));                     \
                } else if (kk < 3) {                                             \
                    ldsm4(&fb[(kk + 1) & 1][0], cur + (bOff[0] ^ xn));           \
                    ldsm4(&fb[(kk + 1) & 1][4], cur + (bOff[1] ^ xn));           \
                    ldsm4(fa[np], cur + (aOff[0] ^ xn));                         \
                }                                                                \
                uint32_t* B = fb[kk & 1];                                        \
                mma16816(acc[mi][0], fa[p], B + 0);                              \
                mma16816(acc[mi][1], fa[p], B + 2);                              \
                mma16816(acc[mi][2], fa[p], B + 4);                              \
                mma16816(acc[mi][3], fa[p], B + 6);                              \
            }                                                                    \
        }                                                                        \
        cur = stg[(i + 1) % NSTAGE];                                             \
        nxt = (nxt + 1) % NSTAGE;                                                \
    }                                                                            \
    __syncthreads();                                                             \
    float* tile = (float*)(smraw + (smb - smem_u32(smraw)));                     \
    {                                                                            \
        const int r0 = lid >> 2;                                                 \
        const int c0 = (lid & 3) * 2;                                            \
        _Pragma("unroll")                                                        \
        for (int mi = 0; mi < 4; mi++)                                           \
            _Pragma("unroll")                                                    \
            for (int ni = 0; ni < 4; ni++) {                                     \
                int m = wm + mi * 16 + r0;                                       \
                int n = wn + ni * 8 + c0;                                        \
                tile[m * 129 + n]           = acc[mi][ni][0];                    \
                tile[m * 129 + n + 1]       = acc[mi][ni][1];                    \
                tile[(m + 8) * 129 + n]     = acc[mi][ni][2];                    \
                tile[(m + 8) * 129 + n + 1] = acc[mi][ni][3];                    \
            }                                                                    \
    }                                                                            \
    __syncthreads();

#define GEMM_BODY(Aptr, Bptr, Kdim) GEMM_BODY2(Aptr, Bptr, Kdim, Kdim)

// ---------------- M = Wq Wk^T split-K with fused last-CTA reduction ---------
__global__ void __launch_bounds__(256, 2)
gemm_wm(const __half* __restrict__ Wq, const __half* __restrict__ Wk,
        float* __restrict__ Mpart, int* __restrict__ cnt,
        __half* __restrict__ Mt)
{
    GEMM_BODY2(Wq + blockIdx.z * WMKLEN, Wk + blockIdx.z * WMKLEN, DIM, WMKLEN)

    float* dst = Mpart + (long)z * DIM * DIM;
    for (int idx = tid; idx < TILE * TILE; idx += 256) {
        int n = idx >> 7, mm = idx & 127;
        dst[(long)(n0 + n) * DIM + m0 + mm] = tile[mm * 129 + n];
    }

    // last CTA for this (x,y) tile sums the WMSPLIT partials -> fp16 Mt
    __threadfence();
    __shared__ int lastFlag;
    const int tix = blockIdx.y * 8 + blockIdx.x;
    if (tid == 0) {
        int c = atomicAdd(&cnt[tix], 1);
        lastFlag = (c == WMSPLIT - 1) ? 1 : 0;
    }
    __syncthreads();
    if (lastFlag) {
        __threadfence();   // acquire: partials from other CTAs now visible
        for (int idx = tid; idx < TILE * TILE; idx += 256) {
            int n = idx >> 7, mm = idx & 127;
            long o = (long)(n0 + n) * DIM + m0 + mm;
            float s = 0.0f;
            #pragma unroll
            for (int zz = 0; zz < WMSPLIT; zz++)
                s += Mpart[(long)zz * DIM * DIM + o];
            Mt[o] = __float2half(s);
        }
        __syncthreads();
        if (tid == 0) cnt[tix] = 0;   // self-reset for next graph replay
    }
}

// ---------------- proj: z=0: G = x M (plain); z=1: Vt = (x Wv + bv)^T -------
__global__ void __launch_bounds__(256, 2)
gemm_proj(const __half* __restrict__ A, const __half* __restrict__ Bmt,
          const __half* __restrict__ Bwv, const float* __restrict__ bv,
          __half* __restrict__ oG, __half* __restrict__ oVt)
{
    GEMM_BODY(A, (blockIdx.z == 0 ? Bmt : Bwv), DIM)

    if (z == 0) {
        for (int idx = tid; idx < TILE * TILE; idx += 256) {
            int r = idx >> 7, c = idx & 127;
            oG[(long)(m0 + r) * DKV + n0 + c] = __float2half(tile[r * 129 + c]);
        }
    } else {
        const int b = m0 >> 11, seq0 = m0 & 2047;
        for (int idx = tid; idx < TILE * TILE; idx += 256) {
            int n = idx >> 7, mm = idx & 127;
            float v = tile[mm * 129 + n] + bv[n0 + n];
            oVt[(long)b * DKV * SEQ + (long)(n0 + n) * SEQ + seq0 + mm] = __float2half(v);
        }
    }
}

// ---------------- scores: E = exp((G x^T + t[p]) / 32 + mask) fp16 ----------
__global__ void __launch_bounds__(256, 2)
gemm_scores(const __half* __restrict__ G, const __half* __restrict__ X,
            const float* __restrict__ mask, const float* __restrict__ tv,
            __half* __restrict__ Eh, float* __restrict__ rsum)
{
    GEMM_BODY(G + (long)blockIdx.z * SEQ * DKV,
              X + (long)blockIdx.z * SEQ * DIM, DIM)

    const long bo = (long)z * SEQ * SEQ;
    for (int idx = tid; idx < TILE * TILE; idx += 256) {
        int r = idx >> 7, c = idx & 127;
        long o = bo + (long)(m0 + r) * SEQ + n0 + c;
        float s = tile[r * 129 + c] + tv[(z << 11) + n0 + c];
        float e = __expf(__fmaf_rn(s, 0.03125f, mask[o]));
        __half eh = __float2half(e);
        Eh[o] = eh;
        tile[r * 129 + c] = __half2float(eh);
    }
    __syncthreads();
    if (tid < 128) {
        float s = 0.0f;
        #pragma unroll 8
        for (int c = 0; c < 128; c++) s += tile[tid * 129 + c];
        rsum[((long)(z << 11) + m0 + tid) * 16 + blockIdx.x] = s;
    }
}

// ---------------- AV GEMM: out = inv[row] * (E @ V); inv from rsum ----------
__global__ void __launch_bounds__(256, 2)
gemm_av(const __half* __restrict__ E, const __half* __restrict__ Vt,
        const float* __restrict__ rsum, float* __restrict__ outF)
{
    GEMM_BODY(E + (long)blockIdx.z * SEQ * SEQ,
              Vt + (long)blockIdx.z * DKV * SEQ, SEQ)

    // per-row 1/sum computed locally from the 16 rsum partials (L2-hot)
    float* sinv = tile + 128 * 129;
    if (tid < 128) {
        const float* rs = rsum + ((long)((z << 11) + m0 + tid)) * 16;
        float s = 0.0f;
        #pragma unroll
        for (int t = 0; t < 16; t++) s += rs[t];
        sinv[tid] = 1.0f / s;
    }
    __syncthreads();

    const long bo = (long)z * SEQ * DKV;
    for (int idx = tid; idx < TILE * TILE; idx += 256) {
        int r = idx >> 7, c = idx & 127;
        outF[bo + (long)(m0 + r) * DKV + n0 + c] = tile[r * 129 + c] * sinv[r];
    }
}

// ---------------- fused: x -> fp16 + t[row] = x_row . wt (warp per row) -----
__global__ void __launch_bounds__(256)
conv_x_t(const float* __restrict__ x, const float* __restrict__ wt,
         __half* __restrict__ x16, float* __restrict__ tOut)
{
    const int w   = threadIdx.x >> 5;
    const int l   = threadIdx.x & 31;
    const int row = blockIdx.x * 8 + w;
    const float4* xr = (const float4*)(x + (long)row * DIM);
    const float4* w4 = (const float4*)wt;
    __half2* o2 = (__half2*)(x16 + (long)row * DIM);

    float acc = 0.0f;
    #pragma unroll
    for (int j = 0; j < 8; j++) {
        int i = l + j * 32;
        float4 v = xr[i];
        float4 ww = w4[i];
        o2[i * 2]     = __floats2half2_rn(v.x, v.y);
        o2[i * 2 + 1] = __floats2half2_rn(v.z, v.w);
        acc += v.x * ww.x + v.y * ww.y + v.z * ww.z + v.w * ww.w;
    }
    #pragma unroll
    for (int s = 16; s > 0; s >>= 1)
        acc += __shfl_down_sync(0xffffffff, acc, s);
    if (l == 0) tOut[row] = acc;
}

// ---------------- fused: Wq/Wk -> fp16 + wt = Wk bq -------------------------
__global__ void __launch_bounds__(256)
convw_dot(const float* __restrict__ Wq, const float* __restrict__ Wk,
          const float* __restrict__ bq,
          __half* __restrict__ oq, __half* __restrict__ ok,
          float* __restrict__ wt)
{
    __shared__ float red[256];
    const int d = blockIdx.x;
    const int t = threadIdx.x;
    const float* W = blockIdx.y ? Wk : Wq;
    __half* o      = blockIdx.y ? ok : oq;

    float4 v = ((const float4*)(W + (long)d * DKV))[t];
    __half2* o2 = (__half2*)(o + (long)d * DKV);
    o2[t * 2]     = __floats2half2_rn(v.x, v.y);
    o2[t * 2 + 1] = __floats2half2_rn(v.z, v.w);

    if (blockIdx.y) {
        float4 b = ((const float4*)bq)[t];
        red[t] = v.x * b.x + v.y * b.y + v.z * b.z + v.w * b.w;
        __syncthreads();
        #pragma unroll
        for (int k = 128; k > 0; k >>= 1) {
            if (t < k) red[t] += red[t + k];
            __syncthreads();
        }
        if (t == 0) wt[d] = red[0];
    }
}

// ---------------- transpose + convert Wv ------------------------------------
__global__ void __launch_bounds__(256)
tconv_wv(const float* __restrict__ in, __half* __restrict__ out)
{
    __shared__ float t[32][33];
    const int bx = blockIdx.x * 32, by = blockIdx.y * 32;
    const int tx = threadIdx.x, ty = threadIdx.y;       // block (32,8)
    #pragma unroll
    for (int k = 0; k < 32; k += 8)
        t[ty + k][tx] = in[(long)(by + ty + k) * DKV + bx + tx];
    __syncthreads();
    #pragma unroll
    for (int k = 0; k < 32; k += 8)
        out[(long)(bx + ty + k) * DIM + by + tx] = __float2half(t[tx][ty + k]);
}

// ---------------------------------------------------------------------------
extern "C" void kernel_launch(void* const* d_in, const int* in_sizes, int n_in,
                              void* d_out, int out_size)
{
    const float* x    = (const float*)d_in[0];
    const float* mask = (const float*)d_in[1];
    const float* Wq   = (const float*)d_in[2];
    const float* bq   = (const float*)d_in[3];
    const float* Wk   = (const float*)d_in[4];
    const float* bk   = (const float*)d_in[5];
    const float* Wv   = (const float*)d_in[6];
    const float* bv   = (const float*)d_in[7];
    float* out = (float*)d_out;
    (void)bk;   // cancels in softmax (u[q], c terms)

    __half *x16, *wq16, *wk16, *wvt16, *mt16, *g16, *vt16, *Ep;
    float *rsp, *wtp, *tp, *mpp;
    int* cntp;
    cudaGetSymbolAddress((void**)&x16,   g_x16);
    cudaGetSymbolAddress((void**)&wq16,  g_wq16);
    cudaGetSymbolAddress((void**)&wk16,  g_wk16);
    cudaGetSymbolAddress((void**)&wvt16, g_wvt16);
    cudaGetSymbolAddress((void**)&mt16,  g_mt16);
    cudaGetSymbolAddress((void**)&mpp,   g_mpart);
    cudaGetSymbolAddress((void**)&cntp,  g_wmcnt);
    cudaGetSymbolAddress((void**)&g16,   g_g16);
    cudaGetSymbolAddress((void**)&vt16,  g_vt16);
    cudaGetSymbolAddress((void**)&Ep,    g_E);
    cudaGetSymbolAddress((void**)&rsp,   g_rsum);
    cudaGetSymbolAddress((void**)&wtp,   g_wt);
    cudaGetSymbolAddress((void**)&tp,    g_t);

    cudaFuncSetAttribute(gemm_wm,     cudaFuncAttributeMaxDynamicSharedMemorySize, SMEM_BYTES);
    cudaFuncSetAttribute(gemm_proj,   cudaFuncAttributeMaxDynamicSharedMemorySize, SMEM_BYTES);
    cudaFuncSetAttribute(gemm_scores, cudaFuncAttributeMaxDynamicSharedMemorySize, SMEM_BYTES);
    cudaFuncSetAttribute(gemm_av,     cudaFuncAttributeMaxDynamicSharedMemorySize, SMEM_BYTES);

    // 1) weight conversion + wt = Wk bq; x conversion fused with t = x wt
    {
        dim3 gw(DIM, 2);
        convw_dot<<<gw, 256>>>(Wq, Wk, bq, wq16, wk16, wtp);
        dim3 tb(32, 8), tg(32, 32);
        tconv_wv<<<tg, tb>>>(Wv, wvt16);
        conv_x_t<<<MTOT / 8, 256>>>(x, wtp, x16, tp);
    }

    dim3 blk(256);

    // 2) M = Wq Wk^T via split-K=8; reduction fused (last CTA per tile)
    {
        dim3 g(DIM / TILE, DIM / TILE, WMSPLIT);
        gemm_wm<<<g, blk, SMEM_BYTES>>>(wq16, wk16, mpp, cntp, mt16);
    }

    // 3) z=0: G = x M;  z=1: Vt = (x Wv + bv)^T
    {
        dim3 g(DKV / TILE, MTOT / TILE, 2);
        gemm_proj<<<g, blk, SMEM_BYTES>>>(x16, mt16, wvt16, bv, g16, vt16);
    }

    // 4) E = exp((G x^T + t)/32 + mask) fp16, per-tile row sums
    {
        dim3 g(SEQ / TILE, SEQ / TILE, BATCH);
        gemm_scores<<<g, blk, SMEM_BYTES>>>(g16, x16, mask, tp, Ep, rsp);
    }

    // 5) out = inv * (E @ V), inv folded into epilogue
    {
        dim3 g(DKV / TILE, SEQ / TILE, BATCH);
        gemm_av<<<g, blk, SMEM_BYTES>>>(Ep, vt16, rsp, out);
    }
}

// round 17
// speedup vs baseline: 1.0707x; 1.0707x over previous
#include <cuda_runtime.h>
#include <cuda_fp16.h>
#include <cstdint>
#include <math.h>

// ---------------------------------------------------------------------------
// Fixed problem: B=4, S=2048, D=DK=1024. M = B*S = 8192.
// R17: revert R16's fused wm-reduction (tail-latency regression). Structure =
// R15 (split-K=4 gemm_wm + separate reduce_m) + warp-per-row conv_x_t.
// Engine/algebra frozen (fp16 HMMA, x M x^T scores, softmax-invariant prune).
// ---------------------------------------------------------------------------
#define BATCH 4
#define SEQ   2048
#define DIM   1024
#define DKV   1024
#define MTOT  (BATCH * SEQ)

#define TILE  128
#define KC    64          // fp16 elements per K-chunk (128B rows, SW128)
#define WMSPLIT 4
#define WMKLEN  (DIM / WMSPLIT)   // 256

// ---------------- scratch (device globals; no allocation) -------------------
__device__ __half g_x16[(size_t)MTOT * DIM];
__device__ __half g_wq16[(size_t)DIM * DKV];             // Wq fp16 (plain)
__device__ __half g_wk16[(size_t)DIM * DKV];             // Wk fp16 (plain)
__device__ __half g_wvt16[(size_t)DKV * DIM];            // Wv^T fp16
__device__ __half g_mt16[(size_t)DIM * DIM];             // (Wq Wk^T)^T fp16
__device__ float  g_mpart[(size_t)WMSPLIT * DIM * DIM];  // split-K partials (T)
__device__ __half g_g16[(size_t)MTOT * DIM];             // G = x M
__device__ __half g_vt16[(size_t)MTOT * DKV];            // V^T per batch
__device__ __half g_E [(size_t)BATCH * SEQ * SEQ];       // exp(scores), fp16
__device__ float  g_rsum[(size_t)MTOT * 16];
__device__ float  g_wt[DIM];                             // Wk bq
__device__ float  g_t [(size_t)MTOT];                    // x (Wk bq)

// ---------------- PTX helpers ----------------------------------------------
static __device__ __forceinline__ uint32_t smem_u32(const void* p) {
    uint32_t a;
    asm("{ .reg .u64 t; cvta.to.shared.u64 t, %1; cvt.u32.u64 %0, t; }" : "=r"(a) : "l"(p));
    return a;
}
static __device__ __forceinline__ void cp16(uint32_t dst, const void* src) {
    asm volatile("cp.async.cg.shared.global [%0], [%1], 16;" :: "r"(dst), "l"(src) : "memory");
}
static __device__ __forceinline__ void cp_commit() {
    asm volatile("cp.async.commit_group;" ::: "memory");
}
static __device__ __forceinline__ void ldsm4(uint32_t* r, uint32_t addr) {
    asm volatile("ldmatrix.sync.aligned.m8n8.x4.shared.b16 {%0,%1,%2,%3}, [%4];"
                 : "=r"(r[0]), "=r"(r[1]), "=r"(r[2]), "=r"(r[3]) : "r"(addr));
}
static __device__ __forceinline__ void mma16816(float* c, const uint32_t* a, const uint32_t* b) {
    asm volatile(
        "mma.sync.aligned.m16n8k16.row.col.f32.f16.f16.f32 "
        "{%0,%1,%2,%3}, {%4,%5,%6,%7}, {%8,%9}, {%0,%1,%2,%3};"
        : "+f"(c[0]), "+f"(c[1]), "+f"(c[2]), "+f"(c[3])
        : "r"(a[0]), "r"(a[1]), "r"(a[2]), "r"(a[3]), "r"(b[0]), "r"(b[1]));
}
static __device__ __forceinline__ uint32_t sw128(uint32_t off) {
    return off ^ ((off >> 3) & 0x70);
}

// Stage (32KB): A @0 (16KB), B @16KB. 128 rows x 128B, SW128 swizzle.
#define STAGE_BYTES 32768
#define NSTAGE      3
#define SMEM_BYTES  (1024 + NSTAGE * STAGE_BYTES)

static __device__ __forceinline__ void load_chunk(
    const __half* A, const __half* B, int Kst,
    int m0, int n0, int koff, uint32_t stage, int tid)
{
    #pragma unroll
    for (int j = 0; j < 4; j++) {
        int id = tid + j * 256;                 // 0..1023
        int r  = id >> 3;                       // 0..127
        int cb = (id & 7) << 4;                 // byte col in 128B row
        uint32_t sw = sw128((uint32_t)((r << 7) + cb));
        cp16(stage +         sw, A + (long)(m0 + r) * Kst + koff + (cb >> 1));
        cp16(stage + 16384 + sw, B + (long)(n0 + r) * Kst + koff + (cb >> 1));
    }
    cp_commit();
}

// Shared prolog + pipelined mainloop + accumulator->tile spill (R11 engine).
// Kst = row stride of A/B; Klen = contraction length for this CTA.
#define GEMM_BODY2(Aptr, Bptr, Kst, Klen)                                        \
    extern __shared__ char smraw[];                                              \
    const int tid = threadIdx.x;                                                 \
    const int wid = tid >> 5;                                                    \
    const int lid = tid & 31;                                                    \
    const int z   = blockIdx.z;                                                  \
    const int m0  = blockIdx.y * TILE;                                           \
    const int n0  = blockIdx.x * TILE;                                           \
    const uint32_t smb = (smem_u32(smraw) + 1023u) & ~1023u;                     \
    uint32_t stg[NSTAGE];                                                        \
    _Pragma("unroll")                                                            \
    for (int s = 0; s < NSTAGE; s++) stg[s] = smb + s * STAGE_BYTES;             \
    const int wm = (wid >> 2) * 64;                                              \
    const int wn = (wid & 3) * 32;                                               \
    const int aRow  = wm + (lid & 15);                                           \
    const int aColB = (lid >> 4) << 4;                                           \
    const int bRow  = wn + (((lid >> 4) & 1) << 3) + (lid & 7);                  \
    const int bColB = ((lid >> 3) & 1) << 4;                                     \
    uint32_t aOff[4], bOff[2];                                                   \
    _Pragma("unroll")                                                            \
    for (int t = 0; t < 4; t++)                                                  \
        aOff[t] = sw128((uint32_t)((aRow + t * 16) << 7) + aColB);               \
    _Pragma("unroll")                                                            \
    for (int t = 0; t < 2; t++)                                                  \
        bOff[t] = sw128((uint32_t)((bRow + t * 16) << 7) + bColB) + 16384;       \
    float acc[4][4][4];                                                          \
    _Pragma("unroll")                                                            \
    for (int mi = 0; mi < 4; mi++)                                               \
        _Pragma("unroll")                                                        \
        for (int ni = 0; ni < 4; ni++)                                           \
            _Pragma("unroll")                                                    \
            for (int r = 0; r < 4; r++) acc[mi][ni][r] = 0.0f;                   \
    uint32_t fa[2][4], fb[2][8];                                                 \
    const int NC = (Klen) / KC;                                                  \
    load_chunk((Aptr), (Bptr), (Kst), m0, n0, 0, stg[0], tid);                   \
    load_chunk((Aptr), (Bptr), (Kst), m0, n0, KC, stg[1], tid);                  \
    uint32_t cur = stg[0];                                                       \
    int nxt = 2;                                                                 \
    for (int i = 0; i < NC; i++) {                                               \
        asm volatile("cp.async.wait_group 1;" ::: "memory");                     \
        __syncthreads();                                                         \
        if (i + 2 < NC)                                                          \
            load_chunk((Aptr), (Bptr), (Kst), m0, n0, (i + 2) * KC, stg[nxt], tid); \
        else                                                                     \
            cp_commit();                                                         \
        ldsm4(&fb[0][0], cur + bOff[0]);                                         \
        ldsm4(&fb[0][4], cur + bOff[1]);                                         \
        ldsm4(fa[0],     cur + aOff[0]);                                         \
        _Pragma("unroll")                                                        \
        for (int kk = 0; kk < 4; kk++) {                                         \
            const uint32_t xc = (uint32_t)(kk << 5);                             \
            const uint32_t xn = (uint32_t)((kk + 1) << 5);                       \
            _Pragma("unroll")                                                    \
            for (int mi = 0; mi < 4; mi++) {                                     \
                const int p  = (kk * 4 + mi) & 1;                                \
                const int np = p ^ 1;                                            \
                if (mi < 3) {                                                    \
                    ldsm4(fa[np], cur + (aOff[mi + 1] ^ xc));                     \
                } else if (kk < 3) {                                             \
                    ldsm4(&fb[(kk + 1) & 1][0], cur + (bOff[0] ^ xn));           \
                    ldsm4(&fb[(kk + 1) & 1][4], cur + (bOff[1] ^ xn));           \
                    ldsm4(fa[np], cur + (aOff[0] ^ xn));                         \
                }                                                                \
                uint32_t* B = fb[kk & 1];                                        \
                mma16816(acc[mi][0], fa[p], B + 0);                              \
                mma16816(acc[mi][1], fa[p], B + 2);                              \
                mma16816(acc[mi][2], fa[p], B + 4);                              \
                mma16816(acc[mi][3], fa[p], B + 6);                              \
            }                                                                    \
        }                                                                        \
        cur = stg[(i + 1) % NSTAGE];                                             \
        nxt = (nxt + 1) % NSTAGE;                                                \
    }                                                                            \
    __syncthreads();                                                             \
    float* tile = (float*)(smraw + (smb - smem_u32(smraw)));                     \
    {                                                                            \
        const int r0 = lid >> 2;                                                 \
        const int c0 = (lid & 3) * 2;                                            \
        _Pragma("unroll")                                                        \
        for (int mi = 0; mi < 4; mi++)                                           \
            _Pragma("unroll")                                                    \
            for (int ni = 0; ni < 4; ni++) {                                     \
                int m = wm + mi * 16 + r0;                                       \
                int n = wn + ni * 8 + c0;                                        \
                tile[m * 129 + n]           = acc[mi][ni][0];                    \
                tile[m * 129 + n + 1]       = acc[mi][ni][1];                    \
                tile[(m + 8) * 129 + n]     = acc[mi][ni][2];                    \
                tile[(m + 8) * 129 + n + 1] = acc[mi][ni][3];                    \
            }                                                                    \
    }                                                                            \
    __syncthreads();

#define GEMM_BODY(Aptr, Bptr, Kdim) GEMM_BODY2(Aptr, Bptr, Kdim, Kdim)

// ---------------- M = Wq Wk^T split-K: fp32 transposed partials -------------
__global__ void __launch_bounds__(256, 2)
gemm_wm(const __half* __restrict__ Wq, const __half* __restrict__ Wk,
        float* __restrict__ Mpart)
{
    GEMM_BODY2(Wq + blockIdx.z * WMKLEN, Wk + blockIdx.z * WMKLEN, DIM, WMKLEN)
    float* dst = Mpart + (long)z * DIM * DIM;
    for (int idx = tid; idx < TILE * TILE; idx += 256) {
        int n = idx >> 7, mm = idx & 127;
        dst[(long)(n0 + n) * DIM + m0 + mm] = tile[mm * 129 + n];
    }
}

// ---------------- reduce split-K partials -> fp16 Mt ------------------------
__global__ void __launch_bounds__(256)
reduce_m(const float* __restrict__ Mpart, __half* __restrict__ Mt)
{
    int i = blockIdx.x * 256 + threadIdx.x;      // float4 index, DIM*DIM/4 total
    const float4* p = (const float4*)Mpart;
    const int st = DIM * DIM / 4;
    float4 a = p[i], b = p[i + st], c = p[i + 2 * st], d = p[i + 3 * st];
    float4 s;
    s.x = a.x + b.x + c.x + d.x;
    s.y = a.y + b.y + c.y + d.y;
    s.z = a.z + b.z + c.z + d.z;
    s.w = a.w + b.w + c.w + d.w;
    __half2* o = (__half2*)Mt;
    o[i * 2]     = __floats2half2_rn(s.x, s.y);
    o[i * 2 + 1] = __floats2half2_rn(s.z, s.w);
}

// ---------------- proj: z=0: G = x M (plain); z=1: Vt = (x Wv + bv)^T -------
__global__ void __launch_bounds__(256, 2)
gemm_proj(const __half* __restrict__ A, const __half* __restrict__ Bmt,
          const __half* __restrict__ Bwv, const float* __restrict__ bv,
          __half* __restrict__ oG, __half* __restrict__ oVt)
{
    GEMM_BODY(A, (blockIdx.z == 0 ? Bmt : Bwv), DIM)

    if (z == 0) {
        for (int idx = tid; idx < TILE * TILE; idx += 256) {
            int r = idx >> 7, c = idx & 127;
            oG[(long)(m0 + r) * DKV + n0 + c] = __float2half(tile[r * 129 + c]);
        }
    } else {
        const int b = m0 >> 11, seq0 = m0 & 2047;
        for (int idx = tid; idx < TILE * TILE; idx += 256) {
            int n = idx >> 7, mm = idx & 127;
            float v = tile[mm * 129 + n] + bv[n0 + n];
            oVt[(long)b * DKV * SEQ + (long)(n0 + n) * SEQ + seq0 + mm] = __float2half(v);
        }
    }
}

// ---------------- scores: E = exp((G x^T + t[p]) / 32 + mask) fp16 ----------
__global__ void __launch_bounds__(256, 2)
gemm_scores(const __half* __restrict__ G, const __half* __restrict__ X,
            const float* __restrict__ mask, const float* __restrict__ tv,
            __half* __restrict__ Eh, float* __restrict__ rsum)
{
    GEMM_BODY(G + (long)blockIdx.z * SEQ * DKV,
              X + (long)blockIdx.z * SEQ * DIM, DIM)

    const long bo = (long)z * SEQ * SEQ;
    for (int idx = tid; idx < TILE * TILE; idx += 256) {
        int r = idx >> 7, c = idx & 127;
        long o = bo + (long)(m0 + r) * SEQ + n0 + c;
        float s = tile[r * 129 + c] + tv[(z << 11) + n0 + c];
        float e = __expf(__fmaf_rn(s, 0.03125f, mask[o]));
        __half eh = __float2half(e);
        Eh[o] = eh;
        tile[r * 129 + c] = __half2float(eh);
    }
    __syncthreads();
    if (tid < 128) {
        float s = 0.0f;
        #pragma unroll 8
        for (int c = 0; c < 128; c++) s += tile[tid * 129 + c];
        rsum[((long)(z << 11) + m0 + tid) * 16 + blockIdx.x] = s;
    }
}

// ---------------- AV GEMM: out = inv[row] * (E @ V); inv from rsum ----------
__global__ void __launch_bounds__(256, 2)
gemm_av(const __half* __restrict__ E, const __half* __restrict__ Vt,
        const float* __restrict__ rsum, float* __restrict__ outF)
{
    GEMM_BODY(E + (long)blockIdx.z * SEQ * SEQ,
              Vt + (long)blockIdx.z * DKV * SEQ, SEQ)

    // per-row 1/sum computed locally from the 16 rsum partials (L2-hot)
    float* sinv = tile + 128 * 129;
    if (tid < 128) {
        const float* rs = rsum + ((long)((z << 11) + m0 + tid)) * 16;
        float s = 0.0f;
        #pragma unroll
        for (int t = 0; t < 16; t++) s += rs[t];
        sinv[tid] = 1.0f / s;
    }
    __syncthreads();

    const long bo = (long)z * SEQ * DKV;
    for (int idx = tid; idx < TILE * TILE; idx += 256) {
        int r = idx >> 7, c = idx & 127;
        outF[bo + (long)(m0 + r) * DKV + n0 + c] = tile[r * 129 + c] * sinv[r];
    }
}

// ---------------- fused: x -> fp16 + t[row] = x_row . wt (warp per row) -----
__global__ void __launch_bounds__(256)
conv_x_t(const float* __restrict__ x, const float* __restrict__ wt,
         __half* __restrict__ x16, float* __restrict__ tOut)
{
    const int w   = threadIdx.x >> 5;
    const int l   = threadIdx.x & 31;
    const int row = blockIdx.x * 8 + w;
    const float4* xr = (const float4*)(x + (long)row * DIM);
    const float4* w4 = (const float4*)wt;
    __half2* o2 = (__half2*)(x16 + (long)row * DIM);

    float acc = 0.0f;
    #pragma unroll
    for (int j = 0; j < 8; j++) {
        int i = l + j * 32;
        float4 v = xr[i];
        float4 ww = w4[i];
        o2[i * 2]     = __floats2half2_rn(v.x, v.y);
        o2[i * 2 + 1] = __floats2half2_rn(v.z, v.w);
        acc += v.x * ww.x + v.y * ww.y + v.z * ww.z + v.w * ww.w;
    }
    #pragma unroll
    for (int s = 16; s > 0; s >>= 1)
        acc += __shfl_down_sync(0xffffffff, acc, s);
    if (l == 0) tOut[row] = acc;
}

// ---------------- fused: Wq/Wk -> fp16 + wt = Wk bq -------------------------
__global__ void __launch_bounds__(256)
convw_dot(const float* __restrict__ Wq, const float* __restrict__ Wk,
          const float* __restrict__ bq,
          __half* __restrict__ oq, __half* __restrict__ ok,
          float* __restrict__ wt)
{
    __shared__ float red[256];
    const int d = blockIdx.x;
    const int t = threadIdx.x;
    const float* W = blockIdx.y ? Wk : Wq;
    __half* o      = blockIdx.y ? ok : oq;

    float4 v = ((const float4*)(W + (long)d * DKV))[t];
    __half2* o2 = (__half2*)(o + (long)d * DKV);
    o2[t * 2]     = __floats2half2_rn(v.x, v.y);
    o2[t * 2 + 1] = __floats2half2_rn(v.z, v.w);

    if (blockIdx.y) {
        float4 b = ((const float4*)bq)[t];
        red[t] = v.x * b.x + v.y * b.y + v.z * b.z + v.w * b.w;
        __syncthreads();
        #pragma unroll
        for (int k = 128; k > 0; k >>= 1) {
            if (t < k) red[t] += red[t + k];
            __syncthreads();
        }
        if (t == 0) wt[d] = red[0];
    }
}

// ---------------- transpose + convert Wv ------------------------------------
__global__ void __launch_bounds__(256)
tconv_wv(const float* __restrict__ in, __half* __restrict__ out)
{
    __shared__ float t[32][33];
    const int bx = blockIdx.x * 32, by = blockIdx.y * 32;
    const int tx = threadIdx.x, ty = threadIdx.y;       // block (32,8)
    #pragma unroll
    for (int k = 0; k < 32; k += 8)
        t[ty + k][tx] = in[(long)(by + ty + k) * DKV + bx + tx];
    __syncthreads();
    #pragma unroll
    for (int k = 0; k < 32; k += 8)
        out[(long)(bx + ty + k) * DIM + by + tx] = __float2half(t[tx][ty + k]);
}

// ---------------------------------------------------------------------------
extern "C" void kernel_launch(void* const* d_in, const int* in_sizes, int n_in,
                              void* d_out, int out_size)
{
    const float* x    = (const float*)d_in[0];
    const float* mask = (const float*)d_in[1];
    const float* Wq   = (const float*)d_in[2];
    const float* bq   = (const float*)d_in[3];
    const float* Wk   = (const float*)d_in[4];
    const float* bk   = (const float*)d_in[5];
    const float* Wv   = (const float*)d_in[6];
    const float* bv   = (const float*)d_in[7];
    float* out = (float*)d_out;
    (void)bk;   // cancels in softmax (u[q], c terms)

    __half *x16, *wq16, *wk16, *wvt16, *mt16, *g16, *vt16, *Ep;
    float *rsp, *wtp, *tp, *mpp;
    cudaGetSymbolAddress((void**)&x16,   g_x16);
    cudaGetSymbolAddress((void**)&wq16,  g_wq16);
    cudaGetSymbolAddress((void**)&wk16,  g_wk16);
    cudaGetSymbolAddress((void**)&wvt16, g_wvt16);
    cudaGetSymbolAddress((void**)&mt16,  g_mt16);
    cudaGetSymbolAddress((void**)&mpp,   g_mpart);
    cudaGetSymbolAddress((void**)&g16,   g_g16);
    cudaGetSymbolAddress((void**)&vt16,  g_vt16);
    cudaGetSymbolAddress((void**)&Ep,    g_E);
    cudaGetSymbolAddress((void**)&rsp,   g_rsum);
    cudaGetSymbolAddress((void**)&wtp,   g_wt);
    cudaGetSymbolAddress((void**)&tp,    g_t);

    cudaFuncSetAttribute(gemm_wm,     cudaFuncAttributeMaxDynamicSharedMemorySize, SMEM_BYTES);
    cudaFuncSetAttribute(gemm_proj,   cudaFuncAttributeMaxDynamicSharedMemorySize, SMEM_BYTES);
    cudaFuncSetAttribute(gemm_scores, cudaFuncAttributeMaxDynamicSharedMemorySize, SMEM_BYTES);
    cudaFuncSetAttribute(gemm_av,     cudaFuncAttributeMaxDynamicSharedMemorySize, SMEM_BYTES);

    // 1) weight conversion + wt = Wk bq; x conversion fused with t = x wt
    {
        dim3 gw(DIM, 2);
        convw_dot<<<gw, 256>>>(Wq, Wk, bq, wq16, wk16, wtp);
        dim3 tb(32, 8), tg(32, 32);
        tconv_wv<<<tg, tb>>>(Wv, wvt16);
        conv_x_t<<<MTOT / 8, 256>>>(x, wtp, x16, tp);
    }

    dim3 blk(256);

    // 2) M = Wq Wk^T via split-K=4 (fp32 transposed partials), then reduce
    {
        dim3 g(DIM / TILE, DIM / TILE, WMSPLIT);
        gemm_wm<<<g, blk, SMEM_BYTES>>>(wq16, wk16, mpp);
        reduce_m<<<DIM * DIM / 4 / 256, 256>>>(mpp, mt16);
    }

    // 3) z=0: G = x M;  z=1: Vt = (x Wv + bv)^T
    {
        dim3 g(DKV / TILE, MTOT / TILE, 2);
        gemm_proj<<<g, blk, SMEM_BYTES>>>(x16, mt16, wvt16, bv, g16, vt16);
    }

    // 4) E = exp((G x^T + t)/32 + mask) fp16, per-tile row sums
    {
        dim3 g(SEQ / TILE, SEQ / TILE, BATCH);
        gemm_scores<<<g, blk, SMEM_BYTES>>>(g16, x16, mask, tp, Ep, rsp);
    }

    // 5) out = inv * (E @ V), inv folded into epilogue
    {
        dim3 g(DKV / TILE, SEQ / TILE, BATCH);
        gemm_av<<<g, blk, SMEM_BYTES>>>(Ep, vt16, rsp, out);
    }
}